// round 5
// baseline (speedup 1.0000x reference)
#include <cuda_runtime.h>

// Sobel |gx|+|gy|+eps over (32,1,1024,1024) f32, SAME zero padding.
// Block = 256 threads stages full 1024-wide rows into an 8-slot smem ring
// via cp.async (16B/thread/row), pipeline depth ~5 rows. Compute keeps a
// 3-row rolling register window; each smem row is read exactly once.
// Zero pad columns in smem remove all horizontal edge handling.

#define IMG_W 1024
#define IMG_H 1024
#define RPT   16             // output rows per block
#define RB    (IMG_H / RPT)  // 64 row-blocks per image
#define S     8              // smem ring slots
#define PITCH 1032           // floats per smem row (4128 B, 16B-aligned)
#define DOFF  4              // data starts at float index 4; pads at [3],[1028]

__device__ __forceinline__ void cp_async16(float* dst, const float* src) {
    unsigned sa = (unsigned)__cvta_generic_to_shared(dst);
    asm volatile("cp.async.cg.shared.global [%0], [%1], 16;\n"
                 :: "r"(sa), "l"(src) : "memory");
}
__device__ __forceinline__ void cp_commit() {
    asm volatile("cp.async.commit_group;\n" ::: "memory");
}
template <int N>
__device__ __forceinline__ void cp_wait() {
    asm volatile("cp.async.wait_group %0;\n" :: "n"(N) : "memory");
}

__global__ void __launch_bounds__(256)
sobel_grad_kernel(const float* __restrict__ x, float* __restrict__ out) {
    __shared__ float sm[S * PITCH];

    int tid = threadIdx.x;
    int bid = blockIdx.x;
    int rb  = bid & (RB - 1);        // row block (0..63)
    int n   = bid >> 6;              // image     (0..31)
    int row0 = rb * RPT;

    const float* img = x + (size_t)n * IMG_H * IMG_W;
    float* op = out + (size_t)n * IMG_H * IMG_W
                    + (size_t)row0 * IMG_W + tid * 4;

    // zero the pad columns of every ring slot (never touched by cp.async)
    if (tid < S) {
        sm[tid * PITCH + DOFF - 1]     = 0.0f;
        sm[tid * PITCH + DOFF + IMG_W] = 0.0f;
    }

    // stage row (row0-1+j) into slot j%S; one 16B cp.async per thread
    auto stage = [&](int j) {
        int r = row0 - 1 + j;
        float* dst = &sm[(j & (S - 1)) * PITCH + DOFF + tid * 4];
        if ((unsigned)r < (unsigned)IMG_H) {
            cp_async16(dst, img + (size_t)r * IMG_W + tid * 4);
        } else {
            *reinterpret_cast<float4*>(dst) = make_float4(0.f, 0.f, 0.f, 0.f);
        }
        cp_commit();   // one group per row (empty group if zero-filled)
    };

    // prologue: stage j = 0 .. S-3  (rows row0-1 .. row0+S-4)
    #pragma unroll
    for (int j = 0; j <= S - 3; j++) stage(j);

    cp_wait<S - 4>();      // rows j=0,1 guaranteed arrived
    __syncthreads();

    float top[6], mid[6];
    {
        const float* p0 = &sm[0 * PITCH + DOFF + tid * 4];
        const float* p1 = &sm[1 * PITCH + DOFF + tid * 4];
        float4 a = *reinterpret_cast<const float4*>(p0);
        top[0] = p0[-1]; top[1] = a.x; top[2] = a.y; top[3] = a.z; top[4] = a.w; top[5] = p0[4];
        float4 b = *reinterpret_cast<const float4*>(p1);
        mid[0] = p1[-1]; mid[1] = b.x; mid[2] = b.y; mid[3] = b.z; mid[4] = b.w; mid[5] = p1[4];
    }

    #pragma unroll
    for (int i = 0; i < RPT; i++) {
        // issue next stage: j = i + S - 2 (targets slot (i-2)%S, not read
        // by any thread within one-barrier skew)
        {
            int j = i + S - 2;
            if (j <= RPT + 1) stage(j);
            else              cp_commit();   // keep group count in sync
        }

        cp_wait<S - 4>();    // row j = i+2 (the new bot) has arrived
        __syncthreads();

        float bot[6];
        {
            const float* p = &sm[((i + 2) & (S - 1)) * PITCH + DOFF + tid * 4];
            float4 b = *reinterpret_cast<const float4*>(p);
            bot[0] = p[-1]; bot[1] = b.x; bot[2] = b.y; bot[3] = b.z; bot[4] = b.w; bot[5] = p[4];
        }

        float o0, o1, o2, o3;
        {
            float gx, gy;
            gx = (top[2] - top[0]) + 2.0f * (mid[2] - mid[0]) + (bot[2] - bot[0]);
            gy = (bot[0] - top[0]) + 2.0f * (bot[1] - top[1]) + (bot[2] - top[2]);
            o0 = fabsf(gx) + fabsf(gy) + 1e-5f;
            gx = (top[3] - top[1]) + 2.0f * (mid[3] - mid[1]) + (bot[3] - bot[1]);
            gy = (bot[1] - top[1]) + 2.0f * (bot[2] - top[2]) + (bot[3] - top[3]);
            o1 = fabsf(gx) + fabsf(gy) + 1e-5f;
            gx = (top[4] - top[2]) + 2.0f * (mid[4] - mid[2]) + (bot[4] - bot[2]);
            gy = (bot[2] - top[2]) + 2.0f * (bot[3] - top[3]) + (bot[4] - top[4]);
            o2 = fabsf(gx) + fabsf(gy) + 1e-5f;
            gx = (top[5] - top[3]) + 2.0f * (mid[5] - mid[3]) + (bot[5] - bot[3]);
            gy = (bot[3] - top[3]) + 2.0f * (bot[4] - top[4]) + (bot[5] - top[5]);
            o3 = fabsf(gx) + fabsf(gy) + 1e-5f;
        }
        __stcs(reinterpret_cast<float4*>(op), make_float4(o0, o1, o2, o3));
        op += IMG_W;

        #pragma unroll
        for (int k = 0; k < 6; k++) { top[k] = mid[k]; mid[k] = bot[k]; }
    }
}

extern "C" void kernel_launch(void* const* d_in, const int* in_sizes, int n_in,
                              void* d_out, int out_size) {
    const float* x = (const float*)d_in[0];
    float* out = (float*)d_out;

    int blocks = out_size / (IMG_W * RPT);   // 32 images * 64 row-blocks = 2048
    sobel_grad_kernel<<<blocks, 256>>>(x, out);
}

// round 6
// speedup vs baseline: 1.0336x; 1.0336x over previous
#include <cuda_runtime.h>

// Sobel |gx|+|gy|+eps over (32,1,1024,1024) f32, SAME zero padding.
// Per-thread 4-wide x 16-tall strip, 3-row rolling register window, raw rows
// prefetched 2 iterations ahead into registers, PLUS prefetch.global.L2
// 4 rows ahead (zero register cost) so demand LDGs hit L2 (~240cyc) instead
// of DRAM (~600cyc).

#define IMG_W 1024
#define IMG_H 1024
#define C4    (IMG_W / 4)   // 256 float4 columns per row
#define RPT   16            // output rows per thread
#define RB    (IMG_H / RPT) // 64 row-blocks per image
#define PFD   4             // L2 prefetch distance (rows ahead of reg prefetch)

struct RawRow {
    float4 c;
    float  e;   // lane 0: left halo; lane 31: right halo; others unused
};

__device__ __forceinline__ void l2_prefetch(const float* p) {
    asm volatile("prefetch.global.L2 [%0];" :: "l"(p));
}

__device__ __forceinline__ RawRow load_raw(const float* __restrict__ base,
                                           bool in, int c4, int lane) {
    RawRow o;
    o.c = make_float4(0.f, 0.f, 0.f, 0.f);
    o.e = 0.f;
    if (in) {
        o.c = *reinterpret_cast<const float4*>(base);
        if (lane == 0) {
            if (c4 > 0) o.e = __ldg(base - 1);
        } else if (lane == 31) {
            if (c4 < C4 - 1) o.e = __ldg(base + 4);
        }
    }
    return o;
}

__device__ __forceinline__ void expand(const RawRow& rr, int lane, float v[6]) {
    float left  = __shfl_up_sync(0xFFFFFFFFu, rr.c.w, 1);
    float right = __shfl_down_sync(0xFFFFFFFFu, rr.c.x, 1);
    if (lane == 0)  left  = rr.e;
    if (lane == 31) right = rr.e;
    v[0] = left;
    v[1] = rr.c.x; v[2] = rr.c.y; v[3] = rr.c.z; v[4] = rr.c.w;
    v[5] = right;
}

__global__ void __launch_bounds__(256, 5)
sobel_grad_kernel(const float* __restrict__ x, float* __restrict__ out) {
    int idx  = blockIdx.x * blockDim.x + threadIdx.x;
    int lane = threadIdx.x & 31;
    int c4 = idx & (C4 - 1);          // float4 column  (0..255)
    int t  = idx >> 8;
    int rb = t & (RB - 1);            // row block      (0..63)
    int n  = t >> 6;                  // image index    (0..31)

    int row0 = rb * RPT;
    const float* ibase = x + (size_t)n * IMG_H * IMG_W + (size_t)c4 * 4;
    float*       obase = out + (size_t)n * IMG_H * IMG_W + (size_t)c4 * 4
                             + (size_t)row0 * IMG_W;

    float top[6], mid[6], bot[6];
    RawRow praw;

    // Prologue: rows row0-1 .. row0+1 expanded, row0+2 raw-prefetched,
    // rows row0+3 .. row0+2+PFD prefetched into L2.
    {
        const float* p = ibase + (size_t)(row0 - 1) * IMG_W;
        RawRow r0 = load_raw(p,             row0 - 1 >= 0,     c4, lane);
        RawRow r1 = load_raw(p + IMG_W,     true,              c4, lane);
        RawRow r2 = load_raw(p + 2 * IMG_W, true,              c4, lane);
        praw      = load_raw(p + 3 * IMG_W, row0 + 2 < IMG_H,  c4, lane);
        #pragma unroll
        for (int j = 0; j < PFD; j++) {
            if (row0 + 3 + j < IMG_H)
                l2_prefetch(p + (size_t)(4 + j) * IMG_W);
        }
        expand(r0, lane, top);
        expand(r1, lane, mid);
        expand(r2, lane, bot);
    }

    const float* pf = ibase + (size_t)(row0 + 3) * IMG_W;

    #pragma unroll
    for (int i = 0; i < RPT; i++) {
        // L2 prefetch row row0+i+3+PFD (consumed PFD+2 iterations later).
        if (row0 + i + 3 + PFD < IMG_H)
            l2_prefetch(pf + (size_t)PFD * IMG_W);

        // Register prefetch raw row row0+i+3 (consumed 2 iterations later).
        RawRow nraw;
        if (i < RPT - 2)
            nraw = load_raw(pf, row0 + i + 3 < IMG_H, c4, lane);
        pf += IMG_W;

        float o0, o1, o2, o3;
        {
            float gx, gy;
            gx = (top[2] - top[0]) + 2.0f * (mid[2] - mid[0]) + (bot[2] - bot[0]);
            gy = (bot[0] - top[0]) + 2.0f * (bot[1] - top[1]) + (bot[2] - top[2]);
            o0 = fabsf(gx) + fabsf(gy) + 1e-5f;
            gx = (top[3] - top[1]) + 2.0f * (mid[3] - mid[1]) + (bot[3] - bot[1]);
            gy = (bot[1] - top[1]) + 2.0f * (bot[2] - top[2]) + (bot[3] - top[3]);
            o1 = fabsf(gx) + fabsf(gy) + 1e-5f;
            gx = (top[4] - top[2]) + 2.0f * (mid[4] - mid[2]) + (bot[4] - bot[2]);
            gy = (bot[2] - top[2]) + 2.0f * (bot[3] - top[3]) + (bot[4] - top[4]);
            o2 = fabsf(gx) + fabsf(gy) + 1e-5f;
            gx = (top[5] - top[3]) + 2.0f * (mid[5] - mid[3]) + (bot[5] - bot[3]);
            gy = (bot[3] - top[3]) + 2.0f * (bot[4] - top[4]) + (bot[5] - top[5]);
            o3 = fabsf(gx) + fabsf(gy) + 1e-5f;
        }
        __stcs(reinterpret_cast<float4*>(obase), make_float4(o0, o1, o2, o3));
        obase += IMG_W;

        if (i < RPT - 1) {
            #pragma unroll
            for (int k = 0; k < 6; k++) { top[k] = mid[k]; mid[k] = bot[k]; }
            expand(praw, lane, bot);
            praw = nraw;
        }
    }
}

extern "C" void kernel_launch(void* const* d_in, const int* in_sizes, int n_in,
                              void* d_out, int out_size) {
    const float* x = (const float*)d_in[0];
    float* out = (float*)d_out;

    int total_threads = out_size / (4 * RPT);     // 524288
    int blocks = (total_threads + 255) / 256;     // 2048
    sobel_grad_kernel<<<blocks, 256>>>(x, out);
}